// round 9
// baseline (speedup 1.0000x reference)
#include <cuda_runtime.h>
#include <math.h>

#define N_NODES 20000
#define N_EDGES 640000
#define HID     256
#define IN_FLAT 36
#define EDGE_DIM 8
#define T_DIM   4
#define S_DIM   6
#define N_LAYERS 5
#define OUT_DIM 18

// ---------------- scratch (device globals; no allocation allowed) ----------
__device__ float g_h[N_NODES * HID];
__device__ float g_u[N_NODES * (3 * HID)];
__device__ float g_q[N_NODES * HID];
__device__ float g_k[N_NODES * HID];
__device__ float g_v[N_NODES * HID];
__device__ float g_skip[N_NODES * HID];
__device__ int   g_cnt[N_NODES];
__device__ int   g_rowptr[N_NODES + 1];
__device__ int   g_cursor[N_NODES];
__device__ int   g_perm[N_EDGES];

// ---------------- CSR build -------------------------------------------------
__global__ void zero_cnt_kernel() {
    for (int i = blockIdx.x * blockDim.x + threadIdx.x; i < N_NODES;
         i += gridDim.x * blockDim.x)
        g_cnt[i] = 0;
}

__global__ void count_kernel(const int* __restrict__ dst) {
    int e = blockIdx.x * blockDim.x + threadIdx.x;
    if (e < N_EDGES) atomicAdd(&g_cnt[dst[e]], 1);
}

// scan also initializes g_cursor (exclusive prefix) — cursor_init folded in
__global__ void scan_kernel() {
    __shared__ int sh[1024];
    __shared__ int carry;
    int tid = threadIdx.x;
    if (tid == 0) { carry = 0; g_rowptr[0] = 0; }
    __syncthreads();
    for (int base = 0; base < N_NODES; base += 1024) {
        int i = base + tid;
        int vv = (i < N_NODES) ? g_cnt[i] : 0;
        sh[tid] = vv;
        __syncthreads();
        #pragma unroll
        for (int off = 1; off < 1024; off <<= 1) {
            int t = (tid >= off) ? sh[tid - off] : 0;
            __syncthreads();
            sh[tid] += t;
            __syncthreads();
        }
        if (i < N_NODES) {
            int inc = carry + sh[tid];
            g_rowptr[i + 1] = inc;
            g_cursor[i] = inc - vv;
        }
        __syncthreads();
        if (tid == 0) carry += sh[1023];
        __syncthreads();
    }
}

__global__ void fill_kernel(const int* __restrict__ dst) {
    int e = blockIdx.x * blockDim.x + threadIdx.x;
    if (e < N_EDGES) {
        int pos = atomicAdd(&g_cursor[dst[e]], 1);
        g_perm[pos] = e;
    }
}

// ---------------- embedding: u = [x@W_emb+b | t@W_t+b | s@W_s+b] ------------
__global__ __launch_bounds__(256) void embed_kernel(
    const float* __restrict__ x, const float* __restrict__ t,
    const float* __restrict__ s,
    const float* __restrict__ W_emb, const float* __restrict__ b_emb,
    const float* __restrict__ W_t, const float* __restrict__ b_t,
    const float* __restrict__ W_s, const float* __restrict__ b_s)
{
    __shared__ float xs[IN_FLAT + T_DIM + S_DIM];
    int node = blockIdx.x;
    int tid  = threadIdx.x;
    if (tid < IN_FLAT) xs[tid] = x[node * IN_FLAT + tid];
    else if (tid < IN_FLAT + T_DIM) xs[tid] = t[node * T_DIM + (tid - IN_FLAT)];
    else if (tid < IN_FLAT + T_DIM + S_DIM)
        xs[tid] = s[node * S_DIM + (tid - IN_FLAT - T_DIM)];
    __syncthreads();

    float a = b_emb[tid];
    #pragma unroll
    for (int k = 0; k < IN_FLAT; k++) a = fmaf(xs[k], W_emb[k * HID + tid], a);
    float tt = b_t[tid];
    #pragma unroll
    for (int k = 0; k < T_DIM; k++) tt = fmaf(xs[IN_FLAT + k], W_t[k * HID + tid], tt);
    float ss = b_s[tid];
    #pragma unroll
    for (int k = 0; k < S_DIM; k++)
        ss = fmaf(xs[IN_FLAT + T_DIM + k], W_s[k * HID + tid], ss);

    g_u[node * 768 + tid]       = a;
    g_u[node * 768 + 256 + tid] = tt;
    g_u[node * 768 + 512 + tid] = ss;
}

// ---------------- tf32 tensor-core GEMM ------------------------------------
__device__ __forceinline__ unsigned f2tf32(float x) {
    unsigned r;
    asm("cvt.rna.tf32.f32 %0, %1;" : "=r"(r) : "f"(x));
    return r;
}

__global__ __launch_bounds__(256) void gemm_tf32_kernel(
    const float* __restrict__ A, int M, int K,
    const float* __restrict__ W0, const float* __restrict__ W1,
    const float* __restrict__ W2, const float* __restrict__ W3,
    const float* __restrict__ b0, const float* __restrict__ b1,
    const float* __restrict__ b2, const float* __restrict__ b3,
    float* __restrict__ C0, float* __restrict__ C1,
    float* __restrict__ C2, float* __restrict__ C3)
{
    const float* W; const float* bias; float* C;
    switch (blockIdx.z) {
        case 0: W = W0; bias = b0; C = C0; break;
        case 1: W = W1; bias = b1; C = C1; break;
        case 2: W = W2; bias = b2; C = C2; break;
        default: W = W3; bias = b3; C = C3; break;
    }

    __shared__ unsigned As[4096];
    __shared__ unsigned Bs[4096];

    int tid = threadIdx.x;
    int lane = tid & 31, warp = tid >> 5;
    int wm = warp >> 1, wn = warp & 1;
    int m0 = blockIdx.y * 128;
    int n0 = blockIdx.x * 128;

    float acc[2][8][4];
    #pragma unroll
    for (int mt = 0; mt < 2; mt++)
        #pragma unroll
        for (int j = 0; j < 8; j++)
            #pragma unroll
            for (int r = 0; r < 4; r++) acc[mt][j][r] = 0.f;

    for (int k0 = 0; k0 < K; k0 += 32) {
        #pragma unroll
        for (int i = 0; i < 4; i++) {
            int idx = tid + 256 * i;
            int row = idx >> 3;
            int c4  = idx & 7;
            int gr = m0 + row;
            float4 av = make_float4(0.f, 0.f, 0.f, 0.f);
            if (gr < M)
                av = *reinterpret_cast<const float4*>(A + (size_t)gr * K + k0 + c4 * 4);
            float vv[4] = {av.x, av.y, av.z, av.w};
            int tm = row >> 4, mr = row & 15;
            #pragma unroll
            for (int j = 0; j < 4; j++) {
                int kl = c4 * 4 + j;
                int tk = kl >> 3, kr = kl & 7;
                int ln = ((mr & 7) << 2) | (kr & 3);
                int rg = (mr >> 3) | ((kr >> 2) << 1);
                As[(((tm * 4 + tk) * 32 + ln) << 2) + rg] = f2tf32(vv[j]);
            }
        }
        #pragma unroll
        for (int i = 0; i < 4; i++) {
            int idx = tid + 256 * i;
            int kl = idx >> 5;
            int c4 = idx & 31;
            float4 bv = *reinterpret_cast<const float4*>(
                W + (size_t)(k0 + kl) * HID + n0 + c4 * 4);
            float vv[4] = {bv.x, bv.y, bv.z, bv.w};
            int tk = kl >> 3, kr = kl & 7;
            #pragma unroll
            for (int j = 0; j < 4; j++) {
                int nl = c4 * 4 + j;
                int tn = nl >> 3, nr = nl & 7;
                int ln = (nr << 2) | (kr & 3);
                int rg = kr >> 2;
                Bs[(((tn * 4 + tk) * 32 + ln) << 1) + rg] = f2tf32(vv[j]);
            }
        }
        __syncthreads();

        #pragma unroll
        for (int tk = 0; tk < 4; tk++) {
            uint4 af[2];
            #pragma unroll
            for (int mt = 0; mt < 2; mt++)
                af[mt] = *reinterpret_cast<const uint4*>(
                    &As[(((wm * 2 + mt) * 4 + tk) * 32 + lane) << 2]);
            uint2 bf[8];
            #pragma unroll
            for (int j = 0; j < 8; j++)
                bf[j] = *reinterpret_cast<const uint2*>(
                    &Bs[(((wn * 8 + j) * 4 + tk) * 32 + lane) << 1]);
            #pragma unroll
            for (int mt = 0; mt < 2; mt++)
                #pragma unroll
                for (int j = 0; j < 8; j++) {
                    asm volatile(
                        "mma.sync.aligned.m16n8k8.row.col.f32.tf32.tf32.f32 "
                        "{%0,%1,%2,%3},{%4,%5,%6,%7},{%8,%9},{%0,%1,%2,%3};\n"
                        : "+f"(acc[mt][j][0]), "+f"(acc[mt][j][1]),
                          "+f"(acc[mt][j][2]), "+f"(acc[mt][j][3])
                        : "r"(af[mt].x), "r"(af[mt].y), "r"(af[mt].z), "r"(af[mt].w),
                          "r"(bf[j].x), "r"(bf[j].y));
                }
        }
        __syncthreads();
    }

    #pragma unroll
    for (int j = 0; j < 8; j++) {
        int col = n0 + (wn * 8 + j) * 8 + 2 * (lane & 3);
        float bx = bias[col], by = bias[col + 1];
        #pragma unroll
        for (int mt = 0; mt < 2; mt++) {
            int r0 = m0 + (wm * 2 + mt) * 16 + (lane >> 2);
            if (r0 < M) {
                float2 o = make_float2(acc[mt][j][0] + bx, acc[mt][j][1] + by);
                *reinterpret_cast<float2*>(C + (size_t)r0 * HID + col) = o;
            }
            int r1 = r0 + 8;
            if (r1 < M) {
                float2 o = make_float2(acc[mt][j][2] + bx, acc[mt][j][3] + by);
                *reinterpret_cast<float2*>(C + (size_t)r1 * HID + col) = o;
            }
        }
    }
}

// ---------------- layernorm + relu (in place on g_h) ------------------------
__global__ __launch_bounds__(256) void ln_relu_kernel(
    const float* __restrict__ gam, const float* __restrict__ bet,
    float* __restrict__ h)
{
    int node = blockIdx.x, tid = threadIdx.x;
    float v = h[node * HID + tid];
    __shared__ float red[8];

    float s1 = v;
    #pragma unroll
    for (int o = 16; o; o >>= 1) s1 += __shfl_xor_sync(0xffffffffu, s1, o);
    if ((tid & 31) == 0) red[tid >> 5] = s1;
    __syncthreads();
    float tot = 0.f;
    #pragma unroll
    for (int i = 0; i < 8; i++) tot += red[i];
    float mu = tot * (1.0f / HID);
    float d = v - mu;

    float s2 = d * d;
    #pragma unroll
    for (int o = 16; o; o >>= 1) s2 += __shfl_xor_sync(0xffffffffu, s2, o);
    __syncthreads();
    if ((tid & 31) == 0) red[tid >> 5] = s2;
    __syncthreads();
    float tot2 = 0.f;
    #pragma unroll
    for (int i = 0; i < 8; i++) tot2 += red[i];
    float var = tot2 * (1.0f / HID);

    float y = d * rsqrtf(var + 1e-5f) * gam[tid] + bet[tid];
    h[node * HID + tid] = fmaxf(y, 0.f);
}

// ---------------- edge attention: warp per destination node -----------------
// Blocked lane-dim mapping: lane owns dims [8*lane, 8*lane+8) -> 2x LDG.128
// per gathered row. Index prefetch pipeline; qe8/qbe computed inline.
__global__ __launch_bounds__(256, 2) void edge_attn_kernel(
    const int* __restrict__ src, const float* __restrict__ edge_attr,
    const float* __restrict__ We, const float* __restrict__ be,
    const float* __restrict__ q, const float* __restrict__ k,
    const float* __restrict__ v, const float* __restrict__ skp,
    float* __restrict__ h_out)
{
    int node = (blockIdx.x * blockDim.x + threadIdx.x) >> 5;
    int lane = threadIdx.x & 31;
    if (node >= N_NODES) return;

    const float4* qp = reinterpret_cast<const float4*>(q + (size_t)node * HID + lane * 8);
    float4 qa = qp[0], qb = qp[1];
    float qr[8] = {qa.x, qa.y, qa.z, qa.w, qb.x, qb.y, qb.z, qb.w};

    // inline qprep: qe8[j] = (We @ q)[j], qbe = be . q
    float part[9];
    #pragma unroll
    for (int j = 0; j < 8; j++) {
        const float* wr = We + j * HID + lane * 8;
        float pq = 0.f;
        #pragma unroll
        for (int i = 0; i < 8; i++) pq = fmaf(qr[i], wr[i], pq);
        part[j] = pq;
    }
    {
        const float* br = be + lane * 8;
        float pq = 0.f;
        #pragma unroll
        for (int i = 0; i < 8; i++) pq = fmaf(qr[i], br[i], pq);
        part[8] = pq;
    }
    #pragma unroll
    for (int o = 16; o; o >>= 1)
        #pragma unroll
        for (int j = 0; j < 9; j++)
            part[j] += __shfl_xor_sync(0xffffffffu, part[j], o);
    float qe8v = (lane < 8) ? part[lane] : 0.f;
    float qbev = part[8];

    float acc[8];
    #pragma unroll
    for (int i = 0; i < 8; i++) acc[i] = 0.f;
    float accE = 0.f, l = 0.f;

    int beg = g_rowptr[node], end = g_rowptr[node + 1];

    // prefetch first index batch
    int e0 = (beg + 0 < end) ? g_perm[beg + 0] : 0;
    int e1 = (beg + 1 < end) ? g_perm[beg + 1] : 0;
    int e2 = (beg + 2 < end) ? g_perm[beg + 2] : 0;
    int e3 = (beg + 3 < end) ? g_perm[beg + 3] : 0;
    int s0 = src[e0], s1 = src[e1], s2 = src[e2], s3 = src[e3];

    for (int p = beg; p < end; p += 4) {
        int np = p + 4;
        // prefetch next batch indices (overlaps the dependent chain)
        int f0 = (np + 0 < end) ? g_perm[np + 0] : 0;
        int f1 = (np + 1 < end) ? g_perm[np + 1] : 0;
        int f2 = (np + 2 < end) ? g_perm[np + 2] : 0;
        int f3 = (np + 3 < end) ? g_perm[np + 3] : 0;
        int t0 = src[f0], t1 = src[f1], t2 = src[f2], t3 = src[f3];

        float ea0 = (lane < 8) ? edge_attr[(size_t)e0 * EDGE_DIM + lane] : 0.f;
        float ea1 = (lane < 8) ? edge_attr[(size_t)e1 * EDGE_DIM + lane] : 0.f;
        float ea2 = (lane < 8) ? edge_attr[(size_t)e2 * EDGE_DIM + lane] : 0.f;
        float ea3 = (lane < 8) ? edge_attr[(size_t)e3 * EDGE_DIM + lane] : 0.f;

        const float4* kp0 = reinterpret_cast<const float4*>(k + (size_t)s0 * HID + lane * 8);
        const float4* kp1 = reinterpret_cast<const float4*>(k + (size_t)s1 * HID + lane * 8);
        const float4* kp2 = reinterpret_cast<const float4*>(k + (size_t)s2 * HID + lane * 8);
        const float4* kp3 = reinterpret_cast<const float4*>(k + (size_t)s3 * HID + lane * 8);
        float4 k0a = kp0[0], k0b = kp0[1];
        float4 k1a = kp1[0], k1b = kp1[1];
        float4 k2a = kp2[0], k2b = kp2[1];
        float4 k3a = kp3[0], k3b = kp3[1];

        // dots (consume k regs)
        float d0 = ea0 * qe8v, d1 = ea1 * qe8v, d2 = ea2 * qe8v, d3 = ea3 * qe8v;
        d0 = fmaf(qr[0], k0a.x, d0); d0 = fmaf(qr[1], k0a.y, d0);
        d0 = fmaf(qr[2], k0a.z, d0); d0 = fmaf(qr[3], k0a.w, d0);
        d0 = fmaf(qr[4], k0b.x, d0); d0 = fmaf(qr[5], k0b.y, d0);
        d0 = fmaf(qr[6], k0b.z, d0); d0 = fmaf(qr[7], k0b.w, d0);
        d1 = fmaf(qr[0], k1a.x, d1); d1 = fmaf(qr[1], k1a.y, d1);
        d1 = fmaf(qr[2], k1a.z, d1); d1 = fmaf(qr[3], k1a.w, d1);
        d1 = fmaf(qr[4], k1b.x, d1); d1 = fmaf(qr[5], k1b.y, d1);
        d1 = fmaf(qr[6], k1b.z, d1); d1 = fmaf(qr[7], k1b.w, d1);
        d2 = fmaf(qr[0], k2a.x, d2); d2 = fmaf(qr[1], k2a.y, d2);
        d2 = fmaf(qr[2], k2a.z, d2); d2 = fmaf(qr[3], k2a.w, d2);
        d2 = fmaf(qr[4], k2b.x, d2); d2 = fmaf(qr[5], k2b.y, d2);
        d2 = fmaf(qr[6], k2b.z, d2); d2 = fmaf(qr[7], k2b.w, d2);
        d3 = fmaf(qr[0], k3a.x, d3); d3 = fmaf(qr[1], k3a.y, d3);
        d3 = fmaf(qr[2], k3a.z, d3); d3 = fmaf(qr[3], k3a.w, d3);
        d3 = fmaf(qr[4], k3b.x, d3); d3 = fmaf(qr[5], k3b.y, d3);
        d3 = fmaf(qr[6], k3b.z, d3); d3 = fmaf(qr[7], k3b.w, d3);

        // issue v loads before the butterfly so they overlap it
        const float4* vp0 = reinterpret_cast<const float4*>(v + (size_t)s0 * HID + lane * 8);
        const float4* vp1 = reinterpret_cast<const float4*>(v + (size_t)s1 * HID + lane * 8);
        const float4* vp2 = reinterpret_cast<const float4*>(v + (size_t)s2 * HID + lane * 8);
        const float4* vp3 = reinterpret_cast<const float4*>(v + (size_t)s3 * HID + lane * 8);
        float4 v0a = vp0[0], v0b = vp0[1];
        float4 v1a = vp1[0], v1b = vp1[1];
        float4 v2a = vp2[0], v2b = vp2[1];
        float4 v3a = vp3[0], v3b = vp3[1];

        #pragma unroll
        for (int o = 16; o; o >>= 1) {
            d0 += __shfl_xor_sync(0xffffffffu, d0, o);
            d1 += __shfl_xor_sync(0xffffffffu, d1, o);
            d2 += __shfl_xor_sync(0xffffffffu, d2, o);
            d3 += __shfl_xor_sync(0xffffffffu, d3, o);
        }
        float pw0 = (p + 0 < end) ? __expf((d0 + qbev) * 0.0625f) : 0.f;
        float pw1 = (p + 1 < end) ? __expf((d1 + qbev) * 0.0625f) : 0.f;
        float pw2 = (p + 2 < end) ? __expf((d2 + qbev) * 0.0625f) : 0.f;
        float pw3 = (p + 3 < end) ? __expf((d3 + qbev) * 0.0625f) : 0.f;

        l += (pw0 + pw1) + (pw2 + pw3);
        accE = fmaf(pw0, ea0, accE);
        accE = fmaf(pw1, ea1, accE);
        accE = fmaf(pw2, ea2, accE);
        accE = fmaf(pw3, ea3, accE);

        acc[0] += fmaf(pw0, v0a.x, pw1 * v1a.x) + fmaf(pw2, v2a.x, pw3 * v3a.x);
        acc[1] += fmaf(pw0, v0a.y, pw1 * v1a.y) + fmaf(pw2, v2a.y, pw3 * v3a.y);
        acc[2] += fmaf(pw0, v0a.z, pw1 * v1a.z) + fmaf(pw2, v2a.z, pw3 * v3a.z);
        acc[3] += fmaf(pw0, v0a.w, pw1 * v1a.w) + fmaf(pw2, v2a.w, pw3 * v3a.w);
        acc[4] += fmaf(pw0, v0b.x, pw1 * v1b.x) + fmaf(pw2, v2b.x, pw3 * v3b.x);
        acc[5] += fmaf(pw0, v0b.y, pw1 * v1b.y) + fmaf(pw2, v2b.y, pw3 * v3b.y);
        acc[6] += fmaf(pw0, v0b.z, pw1 * v1b.z) + fmaf(pw2, v2b.z, pw3 * v3b.z);
        acc[7] += fmaf(pw0, v0b.w, pw1 * v1b.w) + fmaf(pw2, v2b.w, pw3 * v3b.w);

        e0 = f0; e1 = f1; e2 = f2; e3 = f3;
        s0 = t0; s1 = t1; s2 = t2; s3 = t3;
    }

    // epilogue: out = (acc + accE@We + l*be)/l + skip, relu
    float accEj[8];
    #pragma unroll
    for (int j = 0; j < 8; j++)
        accEj[j] = __shfl_sync(0xffffffffu, accE, j);
    float inv = 1.0f / (l + 1e-16f);
    const float* skr = skp + (size_t)node * HID + lane * 8;
    float o[8];
    #pragma unroll
    for (int i = 0; i < 8; i++) {
        int c = lane * 8 + i;
        float corr = l * be[c];
        #pragma unroll
        for (int j = 0; j < 8; j++)
            corr = fmaf(accEj[j], We[j * HID + c], corr);
        o[i] = fmaxf((acc[i] + corr) * inv + skr[i], 0.f);
    }
    float4* op = reinterpret_cast<float4*>(h_out + (size_t)node * HID + lane * 8);
    op[0] = make_float4(o[0], o[1], o[2], o[3]);
    op[1] = make_float4(o[4], o[5], o[6], o[7]);
}

// ---------------- decoder: out = h @ W_dec + b_dec --------------------------
__global__ __launch_bounds__(256) void decoder_kernel(
    const float* __restrict__ h, const float* __restrict__ Wd,
    const float* __restrict__ bd, float* __restrict__ out)
{
    __shared__ float Ws[HID * OUT_DIM];
    for (int i = threadIdx.x; i < HID * OUT_DIM; i += blockDim.x) Ws[i] = Wd[i];
    __syncthreads();
    for (int idx = blockIdx.x * blockDim.x + threadIdx.x; idx < N_NODES * OUT_DIM;
         idx += gridDim.x * blockDim.x) {
        int node = idx / OUT_DIM;
        int c = idx - node * OUT_DIM;
        float sum = bd[c];
        const float* hr = h + (size_t)node * HID;
        #pragma unroll 8
        for (int k2 = 0; k2 < HID; k2++)
            sum = fmaf(hr[k2], Ws[k2 * OUT_DIM + c], sum);
        out[idx] = sum;
    }
}

// ---------------- launch ----------------------------------------------------
extern "C" void kernel_launch(void* const* d_in, const int* in_sizes, int n_in,
                              void* d_out, int out_size)
{
    const float* x        = (const float*)d_in[0];
    const int*   edge_idx = (const int*)  d_in[1];
    const float* edge_attr= (const float*)d_in[2];
    const float* t        = (const float*)d_in[3];
    const float* s        = (const float*)d_in[4];
    const float* W_emb    = (const float*)d_in[5];
    const float* b_emb    = (const float*)d_in[6];
    const float* W_t      = (const float*)d_in[7];
    const float* b_t      = (const float*)d_in[8];
    const float* W_s      = (const float*)d_in[9];
    const float* b_s      = (const float*)d_in[10];
    const float* W_f      = (const float*)d_in[11];
    const float* b_f      = (const float*)d_in[12];
    const float* ln_g     = (const float*)d_in[13];
    const float* ln_b     = (const float*)d_in[14];
    const float* Wq       = (const float*)d_in[15];
    const float* bq       = (const float*)d_in[16];
    const float* Wk       = (const float*)d_in[17];
    const float* bk       = (const float*)d_in[18];
    const float* Wv       = (const float*)d_in[19];
    const float* bv       = (const float*)d_in[20];
    const float* We       = (const float*)d_in[21];
    const float* be       = (const float*)d_in[22];
    const float* Wskip    = (const float*)d_in[23];
    const float* bskip    = (const float*)d_in[24];
    const float* W_dec    = (const float*)d_in[25];
    const float* b_dec    = (const float*)d_in[26];
    float* out = (float*)d_out;

    const int* src = edge_idx;
    const int* dst = edge_idx + N_EDGES;

    float *p_h, *p_u, *p_q, *p_k, *p_v, *p_skip;
    cudaGetSymbolAddress((void**)&p_h, g_h);
    cudaGetSymbolAddress((void**)&p_u, g_u);
    cudaGetSymbolAddress((void**)&p_q, g_q);
    cudaGetSymbolAddress((void**)&p_k, g_k);
    cudaGetSymbolAddress((void**)&p_v, g_v);
    cudaGetSymbolAddress((void**)&p_skip, g_skip);

    // CSR by destination
    zero_cnt_kernel<<<80, 256>>>();
    count_kernel<<<(N_EDGES + 255) / 256, 256>>>(dst);
    scan_kernel<<<1, 1024>>>();
    fill_kernel<<<(N_EDGES + 255) / 256, 256>>>(dst);

    // spatio-temporal embedding + fusion GEMM + LN + relu
    embed_kernel<<<N_NODES, 256>>>(x, t, s, W_emb, b_emb, W_t, b_t, W_s, b_s);
    dim3 fgrid(2, (N_NODES + 127) / 128, 1);
    gemm_tf32_kernel<<<fgrid, 256>>>(p_u, N_NODES, 3 * HID,
        W_f, W_f, W_f, W_f, b_f, b_f, b_f, b_f, p_h, p_h, p_h, p_h);
    ln_relu_kernel<<<N_NODES, 256>>>(ln_g, ln_b, p_h);

    // 5 TransformerConv layers
    dim3 qgrid(2, (N_NODES + 127) / 128, 4);
    int warps_grid = (N_NODES * 32 + 255) / 256;
    for (int l = 0; l < N_LAYERS; l++) {
        const float* We_l = We + (size_t)l * EDGE_DIM * HID;
        const float* be_l = be + l * HID;
        gemm_tf32_kernel<<<qgrid, 256>>>(p_h, N_NODES, HID,
            Wq + (size_t)l * HID * HID, Wk + (size_t)l * HID * HID,
            Wv + (size_t)l * HID * HID, Wskip + (size_t)l * HID * HID,
            bq + l * HID, bk + l * HID, bv + l * HID, bskip + l * HID,
            p_q, p_k, p_v, p_skip);
        edge_attn_kernel<<<warps_grid, 256>>>(
            src, edge_attr, We_l, be_l, p_q, p_k, p_v, p_skip, p_h);
    }

    // decoder
    decoder_kernel<<<592, 256>>>(p_h, W_dec, b_dec, out);
}